// round 3
// baseline (speedup 1.0000x reference)
#include <cuda_runtime.h>
#include <cuda_bf16.h>

// Problem shapes (fixed by the dataset):
//   text:        [16, 2048, 256] f32      d_in[0]
//   const_mat:   [16, 2048, 2048] i32     d_in[1]   (UNUSED: softmax rows sum to 1)
//   const_labels:[16, 2048, 8] i32        d_in[2]
//   emb_table:   [100, 128] f32           d_in[3]
//   attn_W:      [256, 384] f32           d_in[4]   (UNUSED: cancels in softmax)
//   attn_b:      [256] f32                d_in[5]   (UNUSED)
//   fc_W:        [256, 128] f32           d_in[6]
//   fc_b:        [256] f32                d_in[7]
//   out:         [16, 2048, 256] f32
//
// Collapse: out[pos,d] = relu( text[pos,d] + sum_{k=0..7} G[labels[pos,k], d] )
// with G[n,d] = 0.125 * (fc_b[d] + emb_table[n] . fc_W[d]).
//
// R3: L1-throughput-targeted rewrite. G (100 KB) stays L1-resident (text
// streamed with __ldcs); persistent threads with a fully-unrolled 4-iteration
// loop give cross-iteration MLP; 32-bit gather offsets cut ALU issue.

#define CN    100
#define CD    128
#define DIM   256
#define KLBL  8
#define D4    (DIM / 4)

#define FG_BLOCK 256
#define FG_GRID  2048
#define FG_ITERS 4
#define FG_STRIDE (FG_BLOCK * FG_GRID)   // 524288 threads; *4 = 2,097,152 float4s

__device__ float g_G[CN * DIM];  // 100 KB precomputed table

// ---------------------------------------------------------------------------
// Kernel A: G[n,d] = 0.125 * (fc_b[d] + sum_c emb_table[n,c] * fc_W[d,c])
// ---------------------------------------------------------------------------
__global__ void __launch_bounds__(DIM) build_G_kernel(
    const float* __restrict__ emb_table,
    const float* __restrict__ fc_W,
    const float* __restrict__ fc_b)
{
    __shared__ float se[CD];
    const int n = blockIdx.x;
    const int d = threadIdx.x;
    if (d < CD) se[d] = emb_table[n * CD + d];
    __syncthreads();

    const float4* w4 = reinterpret_cast<const float4*>(fc_W + d * CD);
    float acc = fc_b[d];
    #pragma unroll
    for (int c4 = 0; c4 < CD / 4; c4++) {
        float4 w = w4[c4];
        acc = fmaf(se[c4 * 4 + 0], w.x, acc);
        acc = fmaf(se[c4 * 4 + 1], w.y, acc);
        acc = fmaf(se[c4 * 4 + 2], w.z, acc);
        acc = fmaf(se[c4 * 4 + 3], w.w, acc);
    }
    g_G[n * DIM + d] = 0.125f * acc;
}

// ---------------------------------------------------------------------------
// Kernel B: fused gather-add-relu.
// Each thread produces exactly FG_ITERS output float4s at stride FG_STRIDE
// (keeps every access warp-coalesced; pos is warp-uniform since a warp spans
// 32 consecutive float4s = half a 256-dim row).
// ---------------------------------------------------------------------------
__global__ void __launch_bounds__(FG_BLOCK, 6) fused_gather_kernel(
    const float4* __restrict__ text4,
    const int*    __restrict__ labels,
    float4*       __restrict__ out4)
{
    const float4* __restrict__ G4 = reinterpret_cast<const float4*>(g_G);
    const int gid = blockIdx.x * FG_BLOCK + threadIdx.x;

    #pragma unroll
    for (int it = 0; it < FG_ITERS; it++) {
        const int idx = gid + it * FG_STRIDE;
        const int pos = idx >> 6;         // warp-uniform
        const int d4  = idx & (D4 - 1);

        const int4* lb = reinterpret_cast<const int4*>(labels) + (pos << 1);
        const int4 l0 = __ldg(lb + 0);
        const int4 l1 = __ldg(lb + 1);

        // Streaming text read (evict-first: keep G resident in L1).
        const float4 t = __ldcs(text4 + idx);

        // 8 independent L1-resident gathers; 32-bit element offsets.
        const float4 g0 = __ldg(G4 + ((l0.x << 6) + d4));
        const float4 g1 = __ldg(G4 + ((l0.y << 6) + d4));
        const float4 g2 = __ldg(G4 + ((l0.z << 6) + d4));
        const float4 g3 = __ldg(G4 + ((l0.w << 6) + d4));
        const float4 g4 = __ldg(G4 + ((l1.x << 6) + d4));
        const float4 g5 = __ldg(G4 + ((l1.y << 6) + d4));
        const float4 g6 = __ldg(G4 + ((l1.z << 6) + d4));
        const float4 g7 = __ldg(G4 + ((l1.w << 6) + d4));

        float4 r;
        r.x = fmaxf(t.x + ((g0.x + g1.x) + (g2.x + g3.x)) + ((g4.x + g5.x) + (g6.x + g7.x)), 0.0f);
        r.y = fmaxf(t.y + ((g0.y + g1.y) + (g2.y + g3.y)) + ((g4.y + g5.y) + (g6.y + g7.y)), 0.0f);
        r.z = fmaxf(t.z + ((g0.z + g1.z) + (g2.z + g3.z)) + ((g4.z + g5.z) + (g6.z + g7.z)), 0.0f);
        r.w = fmaxf(t.w + ((g0.w + g1.w) + (g2.w + g3.w)) + ((g4.w + g5.w) + (g6.w + g7.w)), 0.0f);

        // Streaming store (output not re-read).
        __stcs(out4 + idx, r);
    }
}

// ---------------------------------------------------------------------------
extern "C" void kernel_launch(void* const* d_in, const int* in_sizes, int n_in,
                              void* d_out, int out_size)
{
    const float* text      = (const float*)d_in[0];
    const int*   labels    = (const int*)  d_in[2];
    const float* emb_table = (const float*)d_in[3];
    const float* fc_W      = (const float*)d_in[6];
    const float* fc_b      = (const float*)d_in[7];
    float*       out       = (float*)d_out;

    build_G_kernel<<<CN, DIM>>>(emb_table, fc_W, fc_b);

    // n4total = in_sizes[0]/4 = 2,097,152 = FG_GRID*FG_BLOCK*FG_ITERS exactly.
    fused_gather_kernel<<<FG_GRID, FG_BLOCK>>>(
        reinterpret_cast<const float4*>(text),
        labels,
        reinterpret_cast<float4*>(out));
}